// round 2
// baseline (speedup 1.0000x reference)
#include <cuda_runtime.h>

// Problem constants: B=4, N=128, M=128, D=256, BD=1024
#define Bsz 4
#define Nn  128
#define Mm  128
#define Dd  256
#define BD  1024

// Scratch: allocation-free per harness rules -> __device__ globals.
__device__ float g_Aw[Dd * Dd];          // 256 KB: Aw[d,e] = sum_k A[d,e,k]*W[k]
__device__ float g_T[Bsz * Nn * Dd];     // 512 KB: T[b,n,e] = sum_d X[b,n,d]*Aw[d,e]

// ---------------------------------------------------------------------------
// Kernel 1 (the 268 MB pass): Aw[de] = dot(A[de, 0:1024], W[0:1024])
// One warp per (d,e) row of 1024 floats. float4 loads, fully coalesced:
// lane i reads float4 #(i + 32*step) -> 512B contiguous per warp per step.
// A is read once and never reused -> streaming loads (__ldcs) to keep the
// small hot tensors (W/Aw/X/Y) resident in L2.
// ---------------------------------------------------------------------------
__global__ void __launch_bounds__(256) k_reduce_A(const float* __restrict__ A,
                                                  const float* __restrict__ W) {
    __shared__ float4 ws[BD / 4];  // 4 KB staged W
    int tid = threadIdx.x;
    ws[tid] = ((const float4*)W)[tid];
    __syncthreads();

    int warp = tid >> 5;
    int lane = tid & 31;
    long de = (long)blockIdx.x * 8 + warp;          // 8 warps/block, 8192 blocks
    const float4* a = (const float4*)(A + de * (long)BD);

    float sum = 0.0f;
#pragma unroll
    for (int i = 0; i < 8; i++) {
        float4 av = __ldcs(&a[lane + 32 * i]);      // non-temporal stream
        float4 wv = ws[lane + 32 * i];
        sum += av.x * wv.x + av.y * wv.y + av.z * wv.z + av.w * wv.w;
    }
#pragma unroll
    for (int o = 16; o; o >>= 1)
        sum += __shfl_xor_sync(0xFFFFFFFFu, sum, o);
    if (lane == 0) g_Aw[de] = sum;
}

// ---------------------------------------------------------------------------
// Kernel 2: T = Xflat[512,256] @ Aw[256,256]
// 32x32 output tile per 16x16 block; each thread computes a 2x2 micro-tile.
// ---------------------------------------------------------------------------
__global__ void __launch_bounds__(256) k_gemm_XA(const float* __restrict__ X) {
    __shared__ float xs[32][33];   // [row][k]
    __shared__ float as[32][33];   // [k][col]
    int tx = threadIdx.x, ty = threadIdx.y;   // 16x16
    int row0 = blockIdx.y * 32;               // b*n flattened (0..511)
    int col0 = blockIdx.x * 32;               // e (0..255)

    float acc00 = 0.f, acc01 = 0.f, acc10 = 0.f, acc11 = 0.f;

    for (int t = 0; t < Dd; t += 32) {
        // each thread loads 2x2 elements of each tile
#pragma unroll
        for (int i = 0; i < 2; i++) {
#pragma unroll
            for (int j = 0; j < 2; j++) {
                xs[ty * 2 + i][tx * 2 + j] = X[(row0 + ty * 2 + i) * Dd + t + tx * 2 + j];
                as[ty * 2 + i][tx * 2 + j] = g_Aw[(t + ty * 2 + i) * Dd + col0 + tx * 2 + j];
            }
        }
        __syncthreads();
#pragma unroll
        for (int k = 0; k < 32; k++) {
            float x0 = xs[ty * 2 + 0][k];
            float x1 = xs[ty * 2 + 1][k];
            float a0 = as[k][tx * 2 + 0];
            float a1 = as[k][tx * 2 + 1];
            acc00 += x0 * a0; acc01 += x0 * a1;
            acc10 += x1 * a0; acc11 += x1 * a1;
        }
        __syncthreads();
    }
    g_T[(row0 + ty * 2 + 0) * Dd + col0 + tx * 2 + 0] = acc00;
    g_T[(row0 + ty * 2 + 0) * Dd + col0 + tx * 2 + 1] = acc01;
    g_T[(row0 + ty * 2 + 1) * Dd + col0 + tx * 2 + 0] = acc10;
    g_T[(row0 + ty * 2 + 1) * Dd + col0 + tx * 2 + 1] = acc11;
}

// ---------------------------------------------------------------------------
// Kernel 3: S[b,n,m] = dot(T[b,n,:], Y[b,m,:]) + bias   (A @ B^T form)
// 32x32 output tile; 2x2 micro-tile per thread. Both operands loaded as rows
// (coalesced); B^T handled by indexing ys[col][k].
// ---------------------------------------------------------------------------
__global__ void __launch_bounds__(256) k_gemm_TYt(const float* __restrict__ Y,
                                                   const float* __restrict__ bias,
                                                   float* __restrict__ out) {
    __shared__ float ts[32][33];   // [n_local][k]
    __shared__ float ys[32][33];   // [m_local][k]
    int tx = threadIdx.x, ty = threadIdx.y;   // 16x16
    int bat = blockIdx.z;
    int n0 = blockIdx.y * 32;
    int m0 = blockIdx.x * 32;
    const float* Tb = g_T + bat * Nn * Dd;
    const float* Yb = Y + bat * Mm * Dd;

    float acc00 = 0.f, acc01 = 0.f, acc10 = 0.f, acc11 = 0.f;

    for (int t = 0; t < Dd; t += 32) {
#pragma unroll
        for (int i = 0; i < 2; i++) {
#pragma unroll
            for (int j = 0; j < 2; j++) {
                ts[ty * 2 + i][tx * 2 + j] = Tb[(n0 + ty * 2 + i) * Dd + t + tx * 2 + j];
                ys[ty * 2 + i][tx * 2 + j] = Yb[(m0 + ty * 2 + i) * Dd + t + tx * 2 + j];
            }
        }
        __syncthreads();
#pragma unroll
        for (int k = 0; k < 32; k++) {
            float t0 = ts[ty * 2 + 0][k];
            float t1 = ts[ty * 2 + 1][k];
            float y0 = ys[tx * 2 + 0][k];
            float y1 = ys[tx * 2 + 1][k];
            acc00 += t0 * y0; acc01 += t0 * y1;
            acc10 += t1 * y0; acc11 += t1 * y1;
        }
        __syncthreads();
    }
    float bv = bias[0];
    float* o = out + bat * Nn * Mm;
    o[(n0 + ty * 2 + 0) * Mm + m0 + tx * 2 + 0] = acc00 + bv;
    o[(n0 + ty * 2 + 0) * Mm + m0 + tx * 2 + 1] = acc01 + bv;
    o[(n0 + ty * 2 + 1) * Mm + m0 + tx * 2 + 0] = acc10 + bv;
    o[(n0 + ty * 2 + 1) * Mm + m0 + tx * 2 + 1] = acc11 + bv;
}

// ---------------------------------------------------------------------------
// Launch. Input order (metadata): X, Y, A, W, b. Output fp32 [B,N,M].
// Graph-capturable: kernel launches only, no sync/alloc.
// ---------------------------------------------------------------------------
extern "C" void kernel_launch(void* const* d_in, const int* in_sizes, int n_in,
                              void* d_out, int out_size) {
    const float* X = (const float*)d_in[0];
    const float* Y = (const float*)d_in[1];
    const float* A = (const float*)d_in[2];
    const float* W = (const float*)d_in[3];
    const float* b = (const float*)d_in[4];
    float* out = (float*)d_out;

    // 1) Aw = A contracted with W over k: 65536 (d,e) pairs, 8 warps/block
    k_reduce_A<<<(Dd * Dd) / 8, 256>>>(A, W);

    // 2) T = X @ Aw : [512,256] = [512,256] x [256,256]
    {
        dim3 blk(16, 16);
        dim3 grd(Dd / 32, (Bsz * Nn) / 32);
        k_gemm_XA<<<grd, blk>>>(X);
    }

    // 3) S = T @ Y^T (+bias), batched over B
    {
        dim3 blk(16, 16);
        dim3 grd(Mm / 32, Nn / 32, Bsz);
        k_gemm_TYt<<<grd, blk>>>(Y, b, out);
    }
}